// round 17
// baseline (speedup 1.0000x reference)
#include <cuda_runtime.h>

// Problem constants
#define B_   64
#define C_   256
#define HW_  4096
#define EMB_ 512
#define NSTREAM (B_ * C_)            // 16384 stream blocks
#define GRID_TOTAL (B_ + NSTREAM)    // 64 chain blocks + stream blocks

// Scratch + sync (allocation-free rule: __device__ globals, zero-init)
__device__ float g_t2[B_ * C_];
__device__ int   g_flag[B_];
__device__ int   g_done;

// ---------------------------------------------------------------------------
// Fused kernel.
//  bid <  B_ : chain block for batch b=bid. Computes t1[b] in SMEM (stage1),
//              block-local __syncthreads, t2[b] to global (stage2), sets
//              g_flag[b]. No inter-block dependencies -> cannot deadlock.
//  bid >= B_ : stream block for bc=bid-B_. Issues its 4 x-loads, spins on
//              g_flag[b] (set within ~3us by a wave-1 chain block), then
//              inline stage-3 dot + broadcast-add (R7-proven form).
// ---------------------------------------------------------------------------
__global__ void __launch_bounds__(256) fused_kernel(
    const float* __restrict__ x,
    const float* __restrict__ cond_emb,    // (B, EMB)
    const float* __restrict__ in_proj_w,   // (3C, C): wv = rows [2C,3C)
    const float* __restrict__ in_proj_b,   // (3C,):   bv = [2C,3C)
    const float* __restrict__ out_w,       // (C, C)
    const float* __restrict__ out_b,       // (C,)
    const float* __restrict__ kv_w,        // (2C, EMB): v-part = rows [C,2C)
    const float* __restrict__ kv_b,        // (2C,)
    float* __restrict__ y)
{
    const int bid  = blockIdx.x;
    const int tid  = threadIdx.x;
    const int lane = tid & 31;
    const int warp = tid >> 5;

    if (bid < B_) {
        // ================= chain block: full chain for batch b ==============
        const int b = bid;
        __shared__ __align__(16) float s_ce[EMB_];
        __shared__ __align__(16) float s_t1[C_];

        for (int i = tid; i < EMB_; i += 256)
            s_ce[i] = cond_emb[(size_t)b * EMB_ + i];
        __syncthreads();

        // Stage 1: warp handles rows [warp*32, warp*32+32). 512-dot each.
        const float4* __restrict__ cev = reinterpret_cast<const float4*>(s_ce);
        #pragma unroll 4
        for (int i = 0; i < 32; i++) {
            const int r = warp * 32 + i;
            const float4* __restrict__ wrow =
                reinterpret_cast<const float4*>(kv_w + (size_t)(C_ + r) * EMB_);
            float acc = 0.f;
            #pragma unroll
            for (int j = 0; j < 4; j++) {
                const float4 a = wrow[lane + 32 * j];
                const float4 c = cev[lane + 32 * j];
                acc += a.x * c.x + a.y * c.y + a.z * c.z + a.w * c.w;
            }
            #pragma unroll
            for (int o = 16; o > 0; o >>= 1)
                acc += __shfl_down_sync(0xffffffffu, acc, o);
            if (lane == 0) s_t1[r] = acc + kv_b[C_ + r];
        }
        __syncthreads();   // block-local: t1[b] complete

        // Stage 2: warp handles rows [warp*32, warp*32+32). 256-dot each.
        const float4* __restrict__ t1v = reinterpret_cast<const float4*>(s_t1);
        const float* __restrict__ wv = in_proj_w + (size_t)2 * C_ * C_;
        #pragma unroll 4
        for (int i = 0; i < 32; i++) {
            const int r = warp * 32 + i;
            const float4* __restrict__ wrow =
                reinterpret_cast<const float4*>(wv + (size_t)r * C_);
            float acc = 0.f;
            #pragma unroll
            for (int j = 0; j < 2; j++) {
                const float4 a = wrow[lane + 32 * j];
                const float4 c = t1v[lane + 32 * j];
                acc += a.x * c.x + a.y * c.y + a.z * c.z + a.w * c.w;
            }
            #pragma unroll
            for (int o = 16; o > 0; o >>= 1)
                acc += __shfl_down_sync(0xffffffffu, acc, o);
            if (lane == 0) g_t2[(size_t)b * C_ + r] = acc + in_proj_b[2 * C_ + r];
        }
        __syncthreads();   // all t2 writes issued

        if (tid == 0) {
            __threadfence();                 // release t2[b]
            atomicExch(&g_flag[b], 1);
        }
    } else {
        // ================= stream block: y[bc,:] = x[bc,:] + a ==============
        const int bc = bid - B_;             // 0 .. B*C-1
        const int b  = bc >> 8;
        const int c  = bc & (C_ - 1);

        const float4* __restrict__ xi =
            reinterpret_cast<const float4*>(x) + (size_t)bc * (HW_ / 4);
        float4* __restrict__ yo =
            reinterpret_cast<float4*>(y) + (size_t)bc * (HW_ / 4);

        // Issue the streaming loads first; they overlap the chain wait.
        float4 v0 = xi[tid];
        float4 v1 = xi[tid + 256];
        float4 v2 = xi[tid + 512];
        float4 v3 = xi[tid + 768];

        // Wait for this batch's chain (wave-1 chain block sets it in ~3us).
        if (tid == 0) {
            volatile int* f = (volatile int*)&g_flag[b];
            while (*f == 0) __nanosleep(64);
            __threadfence();                 // acquire
        }
        __syncthreads();

        // Inline stage 3: a = dot(out_w[c,:], t2[b,:]) + out_b[c]
        float p = out_w[(size_t)c * C_ + tid] * __ldcg(&g_t2[(size_t)b * C_ + tid]);
        #pragma unroll
        for (int o = 16; o > 0; o >>= 1)
            p += __shfl_down_sync(0xffffffffu, p, o);

        __shared__ float s_part[8];
        __shared__ float s_a;
        if (lane == 0) s_part[warp] = p;
        __syncthreads();
        if (tid < 8) {
            float q = s_part[tid];
            q += __shfl_down_sync(0x000000ffu, q, 4);
            q += __shfl_down_sync(0x000000ffu, q, 2);
            q += __shfl_down_sync(0x000000ffu, q, 1);
            if (tid == 0) s_a = q + out_b[c];
        }
        __syncthreads();
        const float a = s_a;

        v0.x += a; v0.y += a; v0.z += a; v0.w += a;
        v1.x += a; v1.y += a; v1.z += a; v1.w += a;
        v2.x += a; v2.y += a; v2.z += a; v2.w += a;
        v3.x += a; v3.y += a; v3.z += a; v3.w += a;
        yo[tid]       = v0;
        yo[tid + 256] = v1;
        yo[tid + 512] = v2;
        yo[tid + 768] = v3;
    }

    // ---- epilogue: ticketed reset so the next graph replay starts clean ----
    __syncthreads();
    if (tid == 0) {
        __threadfence();
        if (atomicAdd(&g_done, 1) == GRID_TOTAL - 1) {
            #pragma unroll
            for (int i = 0; i < B_; i++) g_flag[i] = 0;
            g_done = 0;
            __threadfence();
        }
    }
}

extern "C" void kernel_launch(void* const* d_in, const int* in_sizes, int n_in,
                              void* d_out, int out_size)
{
    // metadata order: x, cond_emb, ln_gamma, ln_beta, in_proj_w, in_proj_b,
    //                 out_w, out_b, kv_w, kv_b
    const float* x         = (const float*)d_in[0];
    const float* cond_emb  = (const float*)d_in[1];
    // ln_gamma/ln_beta provably do not affect the output: softmax over the
    // size-1 KV axis is exactly 1, so q (and thus x_ln) cancels.
    const float* in_proj_w = (const float*)d_in[4];
    const float* in_proj_b = (const float*)d_in[5];
    const float* out_w     = (const float*)d_in[6];
    const float* out_b     = (const float*)d_in[7];
    const float* kv_w      = (const float*)d_in[8];
    const float* kv_b      = (const float*)d_in[9];
    float* y = (float*)d_out;

    fused_kernel<<<GRID_TOTAL, 256>>>(x, cond_emb, in_proj_w, in_proj_b,
                                      out_w, out_b, kv_w, kv_b, y);
}